// round 15
// baseline (speedup 1.0000x reference)
#include <cuda_runtime.h>
#include <cuda_fp16.h>

#define BB 16
#define SS 4096
#define DD 64
#define NH 8
#define NB 64

typedef unsigned long long ull;

// ---- packed f32x2 helpers (hash kernel) ----
#define LDSV2(a,b,addr) asm volatile("ld.shared.v2.u64 {%0,%1},[%2];" : "=l"(a),"=l"(b) : "r"(addr))
#define FMA2(d,a,b,c)   asm("fma.rn.f32x2 %0,%1,%2,%3;" : "=l"(d) : "l"(a),"l"(b),"l"(c))
#define PK2(d,lo,hi)    asm("mov.b64 %0,{%1,%2};" : "=l"(d) : "f"(lo),"f"(hi))
#define UPK2(lo,hi,d)   asm("mov.b64 {%0,%1},%2;" : "=f"(lo),"=f"(hi) : "l"(d))

__device__ __forceinline__ unsigned smaddr(const void* p) {
    unsigned a;
    asm("{ .reg .u64 t; cvta.to.shared.u64 t, %1; cvt.u32.u64 %0, t; }" : "=r"(a) : "l"(p));
    return a;
}
__device__ __forceinline__ void sts128(unsigned a, uint4 v) {
    asm volatile("st.shared.v4.b32 [%0],{%1,%2,%3,%4};" :: "r"(a), "r"(v.x), "r"(v.y), "r"(v.z), "r"(v.w));
}
__device__ __forceinline__ void sts64f(unsigned a, float x, float y) {
    asm volatile("st.shared.v2.f32 [%0],{%1,%2};" :: "r"(a), "f"(x), "f"(y));
}
__device__ __forceinline__ float2 lds64f(unsigned a) {
    float2 r; asm volatile("ld.shared.v2.f32 {%0,%1},[%2];" : "=f"(r.x), "=f"(r.y) : "r"(a)); return r;
}
__device__ __forceinline__ void ldsm_x4(unsigned& d0, unsigned& d1, unsigned& d2, unsigned& d3, unsigned a) {
    asm volatile("ldmatrix.sync.aligned.m8n8.x4.shared.b16 {%0,%1,%2,%3}, [%4];"
                 : "=r"(d0), "=r"(d1), "=r"(d2), "=r"(d3) : "r"(a));
}
__device__ __forceinline__ void ldsm_x4t(unsigned& d0, unsigned& d1, unsigned& d2, unsigned& d3, unsigned a) {
    asm volatile("ldmatrix.sync.aligned.m8n8.x4.trans.shared.b16 {%0,%1,%2,%3}, [%4];"
                 : "=r"(d0), "=r"(d1), "=r"(d2), "=r"(d3) : "r"(a));
}
__device__ __forceinline__ void mma16816(float* c, unsigned a0, unsigned a1, unsigned a2, unsigned a3,
                                         unsigned b0, unsigned b1) {
    asm volatile("mma.sync.aligned.m16n8k16.row.col.f32.f16.f16.f32 "
                 "{%0,%1,%2,%3}, {%4,%5,%6,%7}, {%8,%9}, {%0,%1,%2,%3};"
                 : "+f"(c[0]), "+f"(c[1]), "+f"(c[2]), "+f"(c[3])
                 : "r"(a0), "r"(a1), "r"(a2), "r"(a3), "r"(b0), "r"(b1));
}
__device__ __forceinline__ unsigned h2u(__half2 h) { return *reinterpret_cast<unsigned*>(&h); }

// ---------------- scratch ----------------
__device__ int    g_buckets[BB * NH * SS];
__device__ int    g_st[BB * NH * SS];
__device__ float  g_lse[BB * NH * SS];
__device__ float  g_o[(size_t)BB * NH * SS * DD];
__device__ __half g_kh[(size_t)BB * SS * DD];
__device__ __half g_kl[(size_t)BB * SS * DD];
__device__ __half g_vh[(size_t)BB * SS * DD];
__device__ __half g_vl[(size_t)BB * SS * DD];
__device__ float  g_qn[BB * SS];

// =============================================================================
// K0: prep — normalize K, fp16 hi/lo split of K-hat and V, token-ordered.
// 4 threads per row (16 floats each).
// =============================================================================
__global__ __launch_bounds__(256) void prep_kernel(const float* __restrict__ qk,
                                                   const float* __restrict__ vin)
{
    int b    = blockIdx.y;
    int t    = blockIdx.x * 64 + (threadIdx.x >> 2);
    int part = threadIdx.x & 3;
    size_t rbase = ((size_t)b * SS + t) * DD;

    const float4* src = (const float4*)(qk + rbase) + part * 4;
    float4 x[4];
    float ssq = 0.f;
    #pragma unroll
    for (int c = 0; c < 4; c++) {
        x[c] = src[c];
        ssq += x[c].x * x[c].x + x[c].y * x[c].y + x[c].z * x[c].z + x[c].w * x[c].w;
    }
    ssq += __shfl_xor_sync(0xffffffffu, ssq, 1);
    ssq += __shfl_xor_sync(0xffffffffu, ssq, 2);
    float norm = sqrtf(ssq);
    float inv  = 1.0f / fmaxf(norm, 1e-12f);

    unsigned hi[8], lo[8];
    #pragma unroll
    for (int c = 0; c < 4; c++) {
        float k0 = x[c].x * inv, k1 = x[c].y * inv, k2 = x[c].z * inv, k3 = x[c].w * inv;
        __half2 h01 = __floats2half2_rn(k0, k1), h23 = __floats2half2_rn(k2, k3);
        hi[2*c] = h2u(h01); hi[2*c+1] = h2u(h23);
        float2 b01 = __half22float2(h01), b23 = __half22float2(h23);
        lo[2*c]   = h2u(__floats2half2_rn(k0 - b01.x, k1 - b01.y));
        lo[2*c+1] = h2u(__floats2half2_rn(k2 - b23.x, k3 - b23.y));
    }
    size_t hb = rbase + part * 16;
    *(uint4*)(g_kh + hb)     = make_uint4(hi[0], hi[1], hi[2], hi[3]);
    *(uint4*)(g_kh + hb + 8) = make_uint4(hi[4], hi[5], hi[6], hi[7]);
    *(uint4*)(g_kl + hb)     = make_uint4(lo[0], lo[1], lo[2], lo[3]);
    *(uint4*)(g_kl + hb + 8) = make_uint4(lo[4], lo[5], lo[6], lo[7]);
    if (part == 0) g_qn[b * SS + t] = norm * 0.125f;

    const float4* sv = (const float4*)(vin + rbase) + part * 4;
    #pragma unroll
    for (int c = 0; c < 4; c++) {
        float4 v = sv[c];
        __half2 h01 = __floats2half2_rn(v.x, v.y), h23 = __floats2half2_rn(v.z, v.w);
        hi[2*c] = h2u(h01); hi[2*c+1] = h2u(h23);
        float2 b01 = __half22float2(h01), b23 = __half22float2(h23);
        lo[2*c]   = h2u(__floats2half2_rn(v.x - b01.x, v.y - b01.y));
        lo[2*c+1] = h2u(__floats2half2_rn(v.z - b23.x, v.w - b23.y));
    }
    *(uint4*)(g_vh + hb)     = make_uint4(hi[0], hi[1], hi[2], hi[3]);
    *(uint4*)(g_vh + hb + 8) = make_uint4(hi[4], hi[5], hi[6], hi[7]);
    *(uint4*)(g_vl + hb)     = make_uint4(lo[0], lo[1], lo[2], lo[3]);
    *(uint4*)(g_vl + hb + 8) = make_uint4(lo[4], lo[5], lo[6], lo[7]);
}

// =============================================================================
// K1: LSH hashing (fp32 — bucket argmax must track reference)
// =============================================================================
__global__ __launch_bounds__(256) void hash_kernel(const float* __restrict__ qk,
                                                   const float* __restrict__ rot)
{
    extern __shared__ float rs[];
    int b   = blockIdx.y;
    int tid = threadIdx.x;
    const float* rg = rot + (size_t)b * DD * NH * 32;
    #pragma unroll
    for (int k = 0; k < 64; k++) rs[tid + k * 256] = rg[tid + k * 256];
    __syncthreads();

    int t = blockIdx.x * 256 + tid;
    float q[64];
    const float4* qg = (const float4*)(qk + ((size_t)b * SS + t) * DD);
    #pragma unroll
    for (int c = 0; c < 16; c++) {
        float4 u = qg[c];
        q[4*c] = u.x; q[4*c+1] = u.y; q[4*c+2] = u.z; q[4*c+3] = u.w;
    }

    unsigned rsb = smaddr(rs);

    #pragma unroll 1
    for (int h = 0; h < NH; h++) {
        ull va[16];
        #pragma unroll
        for (int k = 0; k < 16; k++) va[k] = 0ull;
        unsigned hb = rsb + h * 128;
        #pragma unroll 4
        for (int f = 0; f < 64; f++) {
            ull q2; PK2(q2, q[f], q[f]);
            unsigned rb = hb + f * 1024;
            #pragma unroll
            for (int c = 0; c < 8; c++) {
                ull r0, r1; LDSV2(r0, r1, rb + c * 16);
                FMA2(va[2*c],   q2, r0, va[2*c]);
                FMA2(va[2*c+1], q2, r1, va[2*c+1]);
            }
        }
        float vals[32];
        #pragma unroll
        for (int k = 0; k < 16; k++) UPK2(vals[2*k], vals[2*k+1], va[k]);
        float best = vals[0]; int arg = 0;
        #pragma unroll
        for (int i = 1; i < 32; i++) if (vals[i] > best) { best = vals[i]; arg = i; }
        #pragma unroll
        for (int i = 0; i < 32; i++) { float vv = -vals[i]; if (vv > best) { best = vv; arg = 32 + i; } }
        g_buckets[(b * NH + h) * SS + t] = arg;
    }
}

// =============================================================================
// K2: stable counting sort per (b,h)
// =============================================================================
__global__ __launch_bounds__(128) void sort_kernel()
{
    __shared__ int hist[64 * 130];
    __shared__ int base[64];
    int bh  = blockIdx.x;
    int tid = threadIdx.x;

    for (int k = tid; k < 64 * 130; k += 128) hist[k] = 0;
    __syncthreads();

    const int* bks = g_buckets + bh * SS;
    int myb[32];
    #pragma unroll
    for (int k = 0; k < 32; k++) {
        int bb = bks[tid * 32 + k];
        myb[k] = bb;
        hist[bb * 130 + tid] += 1;
    }
    __syncthreads();

    if (tid < 64) {
        int run = 0;
        for (int j = 0; j < 128; j++) {
            int vv = hist[tid * 130 + j];
            hist[tid * 130 + j] = run;
            run += vv;
        }
        base[tid] = run;
    }
    __syncthreads();
    if (tid == 0) {
        int run = 0;
        for (int u = 0; u < 64; u++) { int vv = base[u]; base[u] = run; run += vv; }
    }
    __syncthreads();

    int* st = g_st + bh * SS;
    #pragma unroll
    for (int k = 0; k < 32; k++) {
        int bb  = myb[k];
        int off = hist[bb * 130 + tid];
        hist[bb * 130 + tid] = off + 1;
        st[base[bb] + off] = tid * 32 + k;
    }
}

// =============================================================================
// K3: HMMA attention, phase-split smem (K then V in one hi/lo buffer).
// smem bytes (row stride 72 halves = 144 B):
//   Bhi [128][72]h @0      (18432)  <- K-hat hi, then V hi, then pbuf overlay
//   Blo [128][72]h @18432  (18432)  <- K-hat lo, then V lo
//   qn f[64] @36864 | red f[128] @37120 | ids i[128] @37632
// total 38144 B -> 3 CTAs/SM.
// =============================================================================
#define SM_BLO_OFF 18432
#define SM_QN_OFF  36864
#define SM_RED_OFF 37120
#define SM_IDS_OFF 37632
#define ATT_SMEM_BYTES 38144

__global__ __launch_bounds__(256, 3) void attn_kernel()
{
    extern __shared__ char smc[];
    float* qn  = (float*)(smc + SM_QN_OFF);
    float* red = (float*)(smc + SM_RED_OFF);
    int*   ids = (int*)(smc + SM_IDS_OFF);

    unsigned SB   = smaddr(smc);
    unsigned BhiB = SB;
    unsigned BloB = SB + SM_BLO_OFF;
    unsigned PbB  = SB;

    int b   = blockIdx.y;
    int c   = blockIdx.x;
    int tid = threadIdx.x;
    int h   = c >> 6,  lc  = c & 63;
    int pcn = (c + 511) & 511;
    int ph  = pcn >> 6, plc = pcn & 63;

    if (tid < 128) {
        int rr = tid;
        ids[rr] = (rr < 64) ? g_st[(b * NH + h)  * SS + lc  * 64 + rr]
                            : g_st[(b * NH + ph) * SS + plc * 64 + (rr - 64)];
    }
    __syncthreads();

    // ---- phase 1 gather: K-hat hi/lo fp16 rows -> smem ----
    int gr = tid >> 1, gpart = tid & 1;
    size_t growK = ((size_t)b * SS + ids[gr]) * DD;
    {
        if (tid < 64) qn[tid] = g_qn[b * SS + ids[tid]];
        const uint4* kh = (const uint4*)(g_kh + growK) + gpart * 4;
        const uint4* kl = (const uint4*)(g_kl + growK) + gpart * 4;
        unsigned so = (unsigned)(gr * 144 + gpart * 64);
        #pragma unroll
        for (int cc = 0; cc < 4; cc++) {
            sts128(BhiB + so + cc * 16, kh[cc]);
            sts128(BloB + so + cc * 16, kl[cc]);
        }
    }
    __syncthreads();

    int warp = tid >> 5, lane = tid & 31;
    int g = lane >> 2, tig = lane & 3;
    int mt = warp & 3, jh = warp >> 2;
    int r0 = mt * 16 + g, r1 = r0 + 8;

    int lq  = lane >> 3;
    int lr  = lane & 7;
    int qk8 = (lq & 1) * 8;
    int qf16 = (lq >> 1) * 16;

    unsigned aAdr = (unsigned)((mt * 16 + qk8 + lr) * 144 + qf16);
    unsigned bAdr[4];
    #pragma unroll
    for (int np = 0; np < 4; np++)
        bAdr[np] = (unsigned)((jh * 64 + np * 16 + qk8 + lr) * 144 + qf16);

    // ================= QK^T (3-pass split HMMA) =================
    float C[8][4];
    #pragma unroll
    for (int nt = 0; nt < 8; nt++)
        #pragma unroll
        for (int e = 0; e < 4; e++) C[nt][e] = 0.f;

    #pragma unroll
    for (int kk = 0; kk < 4; kk++) {
        unsigned ah0, ah1, ah2, ah3, al0, al1, al2, al3;
        ldsm_x4(ah0, ah1, ah2, ah3, BhiB + aAdr + kk * 32);
        ldsm_x4(al0, al1, al2, al3, BloB + aAdr + kk * 32);
        #pragma unroll
        for (int np = 0; np < 4; np++) {
            unsigned bh0, bh1, bh2, bh3, bl0, bl1, bl2, bl3;
            ldsm_x4(bh0, bh1, bh2, bh3, BhiB + bAdr[np] + kk * 32);
            ldsm_x4(bl0, bl1, bl2, bl3, BloB + bAdr[np] + kk * 32);
            mma16816(C[2*np],   ah0, ah1, ah2, ah3, bh0, bh2);
            mma16816(C[2*np],   al0, al1, al2, al3, bh0, bh2);
            mma16816(C[2*np],   ah0, ah1, ah2, ah3, bl0, bl2);
            mma16816(C[2*np+1], ah0, ah1, ah2, ah3, bh1, bh3);
            mma16816(C[2*np+1], al0, al1, al2, al3, bh1, bh3);
            mma16816(C[2*np+1], ah0, ah1, ah2, ah3, bl1, bl3);
        }
    }

    // ---- scale + self-mask ----
    float q0 = qn[r0], q1 = qn[r1];
    int idi0 = ids[r0], idi1 = ids[r1];
    #pragma unroll
    for (int nt = 0; nt < 8; nt++) {
        int jj = jh * 64 + nt * 8 + 2 * tig;
        int e0 = ids[jj], e1 = ids[jj + 1];
        C[nt][0] *= q0; C[nt][1] *= q0;
        C[nt][2] *= q1; C[nt][3] *= q1;
        if (idi0 == e0) C[nt][0] = -50000.0f;
        if (idi0 == e1) C[nt][1] = -50000.0f;
        if (idi1 == e0) C[nt][2] = -50000.0f;
        if (idi1 == e1) C[nt][3] = -50000.0f;
    }

    // ---- softmax max-reduce ----
    float m0 = -3.4e38f, m1 = -3.4e38f;
    #pragma unroll
    for (int nt = 0; nt < 8; nt++) {
        m0 = fmaxf(m0, fmaxf(C[nt][0], C[nt][1]));
        m1 = fmaxf(m1, fmaxf(C[nt][2], C[nt][3]));
    }
    m0 = fmaxf(m0, __shfl_xor_sync(0xffffffffu, m0, 1));
    m0 = fmaxf(m0, __shfl_xor_sync(0xffffffffu, m0, 2));
    m1 = fmaxf(m1, __shfl_xor_sync(0xffffffffu, m1, 1));
    m1 = fmaxf(m1, __shfl_xor_sync(0xffffffffu, m1, 2));
    if (tig == 0) { red[r0 * 2 + jh] = m0; red[r1 * 2 + jh] = m1; }
    __syncthreads();    // also: all K LDSM reads complete past this point
    float rm0 = fmaxf(red[r0 * 2], red[r0 * 2 + 1]);
    float rm1 = fmaxf(red[r1 * 2], red[r1 * 2 + 1]);

    // ---- phase 2 gather: V hi/lo fp16 rows into the (dead) K buffers ----
    {
        const uint4* vh = (const uint4*)(g_vh + growK) + gpart * 4;
        const uint4* vl = (const uint4*)(g_vl + growK) + gpart * 4;
        unsigned so = (unsigned)(gr * 144 + gpart * 64);
        #pragma unroll
        for (int cc = 0; cc < 4; cc++) {
            sts128(BhiB + so + cc * 16, vh[cc]);
            sts128(BloB + so + cc * 16, vl[cc]);
        }
    }

    float s0 = 0.f, s1 = 0.f;
    #pragma unroll
    for (int nt = 0; nt < 8; nt++) {
        C[nt][0] = __expf(C[nt][0] - rm0);
        C[nt][1] = __expf(C[nt][1] - rm0);
        C[nt][2] = __expf(C[nt][2] - rm1);
        C[nt][3] = __expf(C[nt][3] - rm1);
        s0 += C[nt][0] + C[nt][1];
        s1 += C[nt][2] + C[nt][3];
    }
    s0 += __shfl_xor_sync(0xffffffffu, s0, 1);
    s0 += __shfl_xor_sync(0xffffffffu, s0, 2);
    s1 += __shfl_xor_sync(0xffffffffu, s1, 1);
    s1 += __shfl_xor_sync(0xffffffffu, s1, 2);
    __syncthreads();    // rm reads done before red overwrite
    if (tig == 0) { red[r0 * 2 + jh] = s0; red[r1 * 2 + jh] = s1; }
    __syncthreads();    // sums ready; V stores complete (pre-2nd-sync)
    float rs0 = red[r0 * 2] + red[r0 * 2 + 1];
    float rs1 = red[r1 * 2] + red[r1 * 2 + 1];
    if (jh == 0 && tig == 0) {
        g_lse[(b * NH + h) * SS + idi0] = rm0 + __logf(rs0);
        g_lse[(b * NH + h) * SS + idi1] = rm1 + __logf(rs1);
    }
    float rinv0 = 1.0f / rs0, rinv1 = 1.0f / rs1;

    // ---- P: C fragments -> A fragments (fp16 hi/lo) ----
    unsigned pah[4][4], pal[4][4];
    #pragma unroll
    for (int kk = 0; kk < 4; kk++) {
        int t0 = 2 * kk, t1 = 2 * kk + 1;
        __half2 hh; float2 bk;
        hh = __floats2half2_rn(C[t0][0], C[t0][1]); pah[kk][0] = h2u(hh); bk = __half22float2(hh);
        pal[kk][0] = h2u(__floats2half2_rn(C[t0][0] - bk.x, C[t0][1] - bk.y));
        hh = __floats2half2_rn(C[t0][2], C[t0][3]); pah[kk][1] = h2u(hh); bk = __half22float2(hh);
        pal[kk][1] = h2u(__floats2half2_rn(C[t0][2] - bk.x, C[t0][3] - bk.y));
        hh = __floats2half2_rn(C[t1][0], C[t1][1]); pah[kk][2] = h2u(hh); bk = __half22float2(hh);
        pal[kk][2] = h2u(__floats2half2_rn(C[t1][0] - bk.x, C[t1][1] - bk.y));
        hh = __floats2half2_rn(C[t1][2], C[t1][3]); pah[kk][3] = h2u(hh); bk = __half22float2(hh);
        pal[kk][3] = h2u(__floats2half2_rn(C[t1][2] - bk.x, C[t1][3] - bk.y));
    }

    // ================= P@V (3-pass split HMMA, ldmatrix.trans B) =================
    float O[8][4];
    #pragma unroll
    for (int nt = 0; nt < 8; nt++)
        #pragma unroll
        for (int e = 0; e < 4; e++) O[nt][e] = 0.f;

    #pragma unroll
    for (int kk = 0; kk < 4; kk++) {
        unsigned vRow = (unsigned)((jh * 64 + kk * 16 + qk8 + lr) * 144 + qf16);
        #pragma unroll
        for (int dp = 0; dp < 4; dp++) {
            unsigned vh0, vh1, vh2, vh3, vl0, vl1, vl2, vl3;
            ldsm_x4t(vh0, vh1, vh2, vh3, BhiB + vRow + dp * 32);
            ldsm_x4t(vl0, vl1, vl2, vl3, BloB + vRow + dp * 32);
            mma16816(O[2*dp],   pah[kk][0], pah[kk][1], pah[kk][2], pah[kk][3], vh0, vh1);
            mma16816(O[2*dp],   pal[kk][0], pal[kk][1], pal[kk][2], pal[kk][3], vh0, vh1);
            mma16816(O[2*dp],   pah[kk][0], pah[kk][1], pah[kk][2], pah[kk][3], vl0, vl1);
            mma16816(O[2*dp+1], pah[kk][0], pah[kk][1], pah[kk][2], pah[kk][3], vh2, vh3);
            mma16816(O[2*dp+1], pal[kk][0], pal[kk][1], pal[kk][2], pal[kk][3], vh2, vh3);
            mma16816(O[2*dp+1], pah[kk][0], pah[kk][1], pah[kk][2], pah[kk][3], vl2, vl3);
        }
    }

    // ---- combine j-halves via pbuf (overlay), write g_o ----
    __syncthreads();
    if (jh == 1) {
        #pragma unroll
        for (int nt = 0; nt < 8; nt++) {
            unsigned o0 = PbB + ((unsigned)(r0 * 66 + nt * 8 + 2 * tig) << 2);
            unsigned o1 = PbB + ((unsigned)(r1 * 66 + nt * 8 + 2 * tig) << 2);
            sts64f(o0, O[nt][0], O[nt][1]);
            sts64f(o1, O[nt][2], O[nt][3]);
        }
    }
    __syncthreads();
    if (jh == 0) {
        size_t ob0 = ((size_t)(b * NH + h) * SS + idi0) * DD;
        size_t ob1 = ((size_t)(b * NH + h) * SS + idi1) * DD;
        #pragma unroll
        for (int nt = 0; nt < 8; nt++) {
            int d = nt * 8 + 2 * tig;
            float2 u0 = lds64f(PbB + ((unsigned)(r0 * 66 + d) << 2));
            float2 u1 = lds64f(PbB + ((unsigned)(r1 * 66 + d) << 2));
            float2 w0 = make_float2((O[nt][0] + u0.x) * rinv0, (O[nt][1] + u0.y) * rinv0);
            float2 w1 = make_float2((O[nt][2] + u1.x) * rinv1, (O[nt][3] + u1.y) * rinv1);
            *(float2*)(g_o + ob0 + d) = w0;
            *(float2*)(g_o + ob1 + d) = w1;
        }
    }
}

// =============================================================================
// K4: combine hash rounds (DRAM-bound, unchanged)
// =============================================================================
__global__ __launch_bounds__(256) void combine_kernel(float* __restrict__ out)
{
    int gid = blockIdx.x * 256 + threadIdx.x;
    int d4  = gid & 15;
    int bt  = gid >> 4;
    int b   = bt >> 12;
    int t   = bt & 4095;

    float l[8]; float m = -3.4e38f;
    #pragma unroll
    for (int h = 0; h < 8; h++) { l[h] = g_lse[(b * NH + h) * SS + t]; m = fmaxf(m, l[h]); }
    float w[8]; float Z = 0.f;
    #pragma unroll
    for (int h = 0; h < 8; h++) { w[h] = __expf(l[h] - m); Z += w[h]; }
    float invZ = 1.0f / Z;

    float4 a = {0,0,0,0};
    #pragma unroll
    for (int h = 0; h < 8; h++) {
        float4 ov = *((const float4*)(g_o + ((size_t)(b * NH + h) * SS + t) * DD) + d4);
        a.x = fmaf(w[h], ov.x, a.x);
        a.y = fmaf(w[h], ov.y, a.y);
        a.z = fmaf(w[h], ov.z, a.z);
        a.w = fmaf(w[h], ov.w, a.w);
    }
    a.x *= invZ; a.y *= invZ; a.z *= invZ; a.w *= invZ;
    ((float4*)out)[(size_t)bt * 16 + d4] = a;
}

// =============================================================================
extern "C" void kernel_launch(void* const* d_in, const int* in_sizes, int n_in,
                              void* d_out, int out_size)
{
    const float* qk  = (const float*)d_in[0];
    const float* v   = (const float*)d_in[1];
    const float* rot = (const float*)d_in[2];
    float* out = (float*)d_out;

    cudaFuncSetAttribute(hash_kernel, cudaFuncAttributeMaxDynamicSharedMemorySize, 65536);
    cudaFuncSetAttribute(attn_kernel, cudaFuncAttributeMaxDynamicSharedMemorySize, ATT_SMEM_BYTES);

    prep_kernel<<<dim3(SS / 64, BB), 256>>>(qk, v);
    hash_kernel<<<dim3(SS / 256, BB), 256, 65536>>>(qk, rot);
    sort_kernel<<<BB * NH, 128>>>();
    attn_kernel<<<dim3(512, BB), 256, ATT_SMEM_BYTES>>>();
    combine_kernel<<<(BB * SS * 16) / 256, 256>>>(out);
}

// round 16
// speedup vs baseline: 1.3638x; 1.3638x over previous
#include <cuda_runtime.h>
#include <cuda_fp16.h>

#define BB 16
#define SS 4096
#define DD 64
#define NH 8
#define NB 64

typedef unsigned long long ull;

// ---- packed f32x2 helpers (hash kernel) ----
#define LDSV2(a,b,addr) asm volatile("ld.shared.v2.u64 {%0,%1},[%2];" : "=l"(a),"=l"(b) : "r"(addr))
#define FMA2(d,a,b,c)   asm("fma.rn.f32x2 %0,%1,%2,%3;" : "=l"(d) : "l"(a),"l"(b),"l"(c))
#define PK2(d,lo,hi)    asm("mov.b64 %0,{%1,%2};" : "=l"(d) : "f"(lo),"f"(hi))
#define UPK2(lo,hi,d)   asm("mov.b64 {%0,%1},%2;" : "=f"(lo),"=f"(hi) : "l"(d))

__device__ __forceinline__ unsigned smaddr(const void* p) {
    unsigned a;
    asm("{ .reg .u64 t; cvta.to.shared.u64 t, %1; cvt.u32.u64 %0, t; }" : "=r"(a) : "l"(p));
    return a;
}
__device__ __forceinline__ void sts32(unsigned a, unsigned v) {
    asm volatile("st.shared.b32 [%0],%1;" :: "r"(a), "r"(v));
}
__device__ __forceinline__ void sts64f(unsigned a, float x, float y) {
    asm volatile("st.shared.v2.f32 [%0],{%1,%2};" :: "r"(a), "f"(x), "f"(y));
}
__device__ __forceinline__ float2 lds64f(unsigned a) {
    float2 r; asm volatile("ld.shared.v2.f32 {%0,%1},[%2];" : "=f"(r.x), "=f"(r.y) : "r"(a)); return r;
}
__device__ __forceinline__ void ldsm_x4(unsigned& d0, unsigned& d1, unsigned& d2, unsigned& d3, unsigned a) {
    asm volatile("ldmatrix.sync.aligned.m8n8.x4.shared.b16 {%0,%1,%2,%3}, [%4];"
                 : "=r"(d0), "=r"(d1), "=r"(d2), "=r"(d3) : "r"(a));
}
__device__ __forceinline__ void ldsm_x4t(unsigned& d0, unsigned& d1, unsigned& d2, unsigned& d3, unsigned a) {
    asm volatile("ldmatrix.sync.aligned.m8n8.x4.trans.shared.b16 {%0,%1,%2,%3}, [%4];"
                 : "=r"(d0), "=r"(d1), "=r"(d2), "=r"(d3) : "r"(a));
}
__device__ __forceinline__ void mma16816(float* c, unsigned a0, unsigned a1, unsigned a2, unsigned a3,
                                         unsigned b0, unsigned b1) {
    asm volatile("mma.sync.aligned.m16n8k16.row.col.f32.f16.f16.f32 "
                 "{%0,%1,%2,%3}, {%4,%5,%6,%7}, {%8,%9}, {%0,%1,%2,%3};"
                 : "+f"(c[0]), "+f"(c[1]), "+f"(c[2]), "+f"(c[3])
                 : "r"(a0), "r"(a1), "r"(a2), "r"(a3), "r"(b0), "r"(b1));
}
__device__ __forceinline__ unsigned h2u(__half2 h) { return *reinterpret_cast<unsigned*>(&h); }

// ---------------- scratch ----------------
__device__ int   g_buckets[BB * NH * SS];
__device__ int   g_st[BB * NH * SS];
__device__ float g_lse[BB * NH * SS];
__device__ float g_o[(size_t)BB * NH * SS * DD];

// =============================================================================
// K1: LSH hashing (fp32 — bucket argmax must track reference)
// =============================================================================
__global__ __launch_bounds__(256) void hash_kernel(const float* __restrict__ qk,
                                                   const float* __restrict__ rot)
{
    extern __shared__ float rs[];
    int b   = blockIdx.y;
    int tid = threadIdx.x;
    const float* rg = rot + (size_t)b * DD * NH * 32;
    #pragma unroll
    for (int k = 0; k < 64; k++) rs[tid + k * 256] = rg[tid + k * 256];
    __syncthreads();

    int t = blockIdx.x * 256 + tid;
    float q[64];
    const float4* qg = (const float4*)(qk + ((size_t)b * SS + t) * DD);
    #pragma unroll
    for (int c = 0; c < 16; c++) {
        float4 u = qg[c];
        q[4*c] = u.x; q[4*c+1] = u.y; q[4*c+2] = u.z; q[4*c+3] = u.w;
    }

    unsigned rsb = smaddr(rs);

    #pragma unroll 1
    for (int h = 0; h < NH; h++) {
        ull va[16];
        #pragma unroll
        for (int k = 0; k < 16; k++) va[k] = 0ull;
        unsigned hb = rsb + h * 128;
        #pragma unroll 4
        for (int f = 0; f < 64; f++) {
            ull q2; PK2(q2, q[f], q[f]);
            unsigned rb = hb + f * 1024;
            #pragma unroll
            for (int c = 0; c < 8; c++) {
                ull r0, r1; LDSV2(r0, r1, rb + c * 16);
                FMA2(va[2*c],   q2, r0, va[2*c]);
                FMA2(va[2*c+1], q2, r1, va[2*c+1]);
            }
        }
        float vals[32];
        #pragma unroll
        for (int k = 0; k < 16; k++) UPK2(vals[2*k], vals[2*k+1], va[k]);
        float best = vals[0]; int arg = 0;
        #pragma unroll
        for (int i = 1; i < 32; i++) if (vals[i] > best) { best = vals[i]; arg = i; }
        #pragma unroll
        for (int i = 0; i < 32; i++) { float vv = -vals[i]; if (vv > best) { best = vv; arg = 32 + i; } }
        g_buckets[(b * NH + h) * SS + t] = arg;
    }
}

// =============================================================================
// K2: stable counting sort per (b,h)
// =============================================================================
__global__ __launch_bounds__(128) void sort_kernel()
{
    __shared__ int hist[64 * 130];
    __shared__ int base[64];
    int bh  = blockIdx.x;
    int tid = threadIdx.x;

    for (int k = tid; k < 64 * 130; k += 128) hist[k] = 0;
    __syncthreads();

    const int* bks = g_buckets + bh * SS;
    int myb[32];
    #pragma unroll
    for (int k = 0; k < 32; k++) {
        int bb = bks[tid * 32 + k];
        myb[k] = bb;
        hist[bb * 130 + tid] += 1;
    }
    __syncthreads();

    if (tid < 64) {
        int run = 0;
        for (int j = 0; j < 128; j++) {
            int vv = hist[tid * 130 + j];
            hist[tid * 130 + j] = run;
            run += vv;
        }
        base[tid] = run;
    }
    __syncthreads();
    if (tid == 0) {
        int run = 0;
        for (int u = 0; u < 64; u++) { int vv = base[u]; base[u] = run; run += vv; }
    }
    __syncthreads();

    int* st = g_st + bh * SS;
    #pragma unroll
    for (int k = 0; k < 32; k++) {
        int bb  = myb[k];
        int off = hist[bb * 130 + tid];
        hist[bb * 130 + tid] = off + 1;
        st[base[bb] + off] = tid * 32 + k;
    }
}

// =============================================================================
// K3: HMMA attention. QK 3-pass fp16 split; PV 2-pass (V hi-only, err ~2^-12).
// smem bytes (row stride 72 halves = 144 B):
//   Khi [128][72]h @0      (18432)  <- pbuf[64][66]f overlay at epilogue
//   Klo [128][72]h @18432  (18432)
//   Vhi [128][72]h @36864  (18432)  (row-major [j][d])
//   qn f[64] @55296 | red f[128] @55552 | ids i[128] @56064
// total 56576 B -> 3 CTAs/SM.
// =============================================================================
#define SM_KLO_OFF 18432
#define SM_VHI_OFF 36864
#define SM_QN_OFF  55296
#define SM_RED_OFF 55552
#define SM_IDS_OFF 56064
#define ATT_SMEM_BYTES 56576

__global__ __launch_bounds__(256, 3) void attn_kernel(const float* __restrict__ qk,
                                                      const float* __restrict__ vin)
{
    extern __shared__ char smc[];
    float* qn  = (float*)(smc + SM_QN_OFF);
    float* red = (float*)(smc + SM_RED_OFF);
    int*   ids = (int*)(smc + SM_IDS_OFF);

    unsigned SB   = smaddr(smc);
    unsigned KhiB = SB;
    unsigned KloB = SB + SM_KLO_OFF;
    unsigned VhiB = SB + SM_VHI_OFF;
    unsigned PbB  = SB;

    int b   = blockIdx.y;
    int c   = blockIdx.x;
    int tid = threadIdx.x;
    int h   = c >> 6,  lc  = c & 63;
    int pcn = (c + 511) & 511;
    int ph  = pcn >> 6, plc = pcn & 63;

    if (tid < 128) {
        int rr = tid;
        ids[rr] = (rr < 64) ? g_st[(b * NH + h)  * SS + lc  * 64 + rr]
                            : g_st[(b * NH + ph) * SS + plc * 64 + (rr - 64)];
    }
    __syncthreads();

    // ---- gather: K-hat hi/lo + V hi (fp16), all row-major, up-front ----
    {
        int r = tid >> 1, part = tid & 1;
        int t = ids[r];
        int f0 = part * 32;
        const float4* srck = (const float4*)(qk  + ((size_t)b * SS + t) * DD) + part * 8;
        const float4* srcv = (const float4*)(vin + ((size_t)b * SS + t) * DD) + part * 8;
        float4 xr[8], vr[8];
        float  ssq = 0.f;
        #pragma unroll
        for (int c4 = 0; c4 < 8; c4++) {
            float4 x = srck[c4]; xr[c4] = x;
            ssq += x.x * x.x + x.y * x.y + x.z * x.z + x.w * x.w;
            vr[c4] = srcv[c4];
        }
        ssq += __shfl_xor_sync(0xffffffffu, ssq, 1);
        float norm = sqrtf(ssq);
        float inv  = 1.0f / fmaxf(norm, 1e-12f);
        #pragma unroll
        for (int c4 = 0; c4 < 8; c4++) {
            float k0 = xr[c4].x * inv, k1 = xr[c4].y * inv;
            float k2 = xr[c4].z * inv, k3 = xr[c4].w * inv;
            unsigned off = ((unsigned)(r * 72 + f0 + 4 * c4)) << 1;
            __half2 h01 = __floats2half2_rn(k0, k1);
            __half2 h23 = __floats2half2_rn(k2, k3);
            sts32(KhiB + off,     h2u(h01));
            sts32(KhiB + off + 4, h2u(h23));
            float2 b01 = __half22float2(h01);
            float2 b23 = __half22float2(h23);
            sts32(KloB + off,     h2u(__floats2half2_rn(k0 - b01.x, k1 - b01.y)));
            sts32(KloB + off + 4, h2u(__floats2half2_rn(k2 - b23.x, k3 - b23.y)));
            // V hi only
            sts32(VhiB + off,     h2u(__floats2half2_rn(vr[c4].x, vr[c4].y)));
            sts32(VhiB + off + 4, h2u(__floats2half2_rn(vr[c4].z, vr[c4].w)));
        }
        if (part == 0 && r < 64) qn[r] = norm * 0.125f;
    }
    __syncthreads();

    int warp = tid >> 5, lane = tid & 31;
    int g = lane >> 2, tig = lane & 3;
    int mt = warp & 3, jh = warp >> 2;
    int r0 = mt * 16 + g, r1 = r0 + 8;

    int lq  = lane >> 3;
    int lr  = lane & 7;
    int qk8 = (lq & 1) * 8;
    int qf16 = (lq >> 1) * 16;

    unsigned aAdr = (unsigned)((mt * 16 + qk8 + lr) * 144 + qf16);
    unsigned bAdr[4];
    #pragma unroll
    for (int np = 0; np < 4; np++)
        bAdr[np] = (unsigned)((jh * 64 + np * 16 + qk8 + lr) * 144 + qf16);

    // ================= QK^T (3-pass split HMMA) =================
    float C[8][4];
    #pragma unroll
    for (int nt = 0; nt < 8; nt++)
        #pragma unroll
        for (int e = 0; e < 4; e++) C[nt][e] = 0.f;

    #pragma unroll
    for (int kk = 0; kk < 4; kk++) {
        unsigned ah0, ah1, ah2, ah3, al0, al1, al2, al3;
        ldsm_x4(ah0, ah1, ah2, ah3, KhiB + aAdr + kk * 32);
        ldsm_x4(al0, al1, al2, al3, KloB + aAdr + kk * 32);
        #pragma unroll
        for (int np = 0; np < 4; np++) {
            unsigned bh0, bh1, bh2, bh3, bl0, bl1, bl2, bl3;
            ldsm_x4(bh0, bh1, bh2, bh3, KhiB + bAdr[np] + kk * 32);
            ldsm_x4(bl0, bl1, bl2, bl3, KloB + bAdr[np] + kk * 32);
            mma16816(C[2*np],   ah0, ah1, ah2, ah3, bh0, bh2);
            mma16816(C[2*np],   al0, al1, al2, al3, bh0, bh2);
            mma16816(C[2*np],   ah0, ah1, ah2, ah3, bl0, bl2);
            mma16816(C[2*np+1], ah0, ah1, ah2, ah3, bh1, bh3);
            mma16816(C[2*np+1], al0, al1, al2, al3, bh1, bh3);
            mma16816(C[2*np+1], ah0, ah1, ah2, ah3, bl1, bl3);
        }
    }

    // ---- scale + self-mask ----
    float q0 = qn[r0], q1 = qn[r1];
    int idi0 = ids[r0], idi1 = ids[r1];
    #pragma unroll
    for (int nt = 0; nt < 8; nt++) {
        int jj = jh * 64 + nt * 8 + 2 * tig;
        int e0 = ids[jj], e1 = ids[jj + 1];
        C[nt][0] *= q0; C[nt][1] *= q0;
        C[nt][2] *= q1; C[nt][3] *= q1;
        if (idi0 == e0) C[nt][0] = -50000.0f;
        if (idi0 == e1) C[nt][1] = -50000.0f;
        if (idi1 == e0) C[nt][2] = -50000.0f;
        if (idi1 == e1) C[nt][3] = -50000.0f;
    }

    // ---- softmax (regs + shfl + cross-warp red) ----
    float m0 = -3.4e38f, m1 = -3.4e38f;
    #pragma unroll
    for (int nt = 0; nt < 8; nt++) {
        m0 = fmaxf(m0, fmaxf(C[nt][0], C[nt][1]));
        m1 = fmaxf(m1, fmaxf(C[nt][2], C[nt][3]));
    }
    m0 = fmaxf(m0, __shfl_xor_sync(0xffffffffu, m0, 1));
    m0 = fmaxf(m0, __shfl_xor_sync(0xffffffffu, m0, 2));
    m1 = fmaxf(m1, __shfl_xor_sync(0xffffffffu, m1, 1));
    m1 = fmaxf(m1, __shfl_xor_sync(0xffffffffu, m1, 2));
    if (tig == 0) { red[r0 * 2 + jh] = m0; red[r1 * 2 + jh] = m1; }
    __syncthreads();
    float rm0 = fmaxf(red[r0 * 2], red[r0 * 2 + 1]);
    float rm1 = fmaxf(red[r1 * 2], red[r1 * 2 + 1]);
    __syncthreads();

    float s0 = 0.f, s1 = 0.f;
    #pragma unroll
    for (int nt = 0; nt < 8; nt++) {
        C[nt][0] = __expf(C[nt][0] - rm0);
        C[nt][1] = __expf(C[nt][1] - rm0);
        C[nt][2] = __expf(C[nt][2] - rm1);
        C[nt][3] = __expf(C[nt][3] - rm1);
        s0 += C[nt][0] + C[nt][1];
        s1 += C[nt][2] + C[nt][3];
    }
    s0 += __shfl_xor_sync(0xffffffffu, s0, 1);
    s0 += __shfl_xor_sync(0xffffffffu, s0, 2);
    s1 += __shfl_xor_sync(0xffffffffu, s1, 1);
    s1 += __shfl_xor_sync(0xffffffffu, s1, 2);
    if (tig == 0) { red[r0 * 2 + jh] = s0; red[r1 * 2 + jh] = s1; }
    __syncthreads();
    float rs0 = red[r0 * 2] + red[r0 * 2 + 1];
    float rs1 = red[r1 * 2] + red[r1 * 2 + 1];
    if (jh == 0 && tig == 0) {
        g_lse[(b * NH + h) * SS + idi0] = rm0 + __logf(rs0);
        g_lse[(b * NH + h) * SS + idi1] = rm1 + __logf(rs1);
    }
    float rinv0 = 1.0f / rs0, rinv1 = 1.0f / rs1;

    // ---- P: C fragments -> A fragments (fp16 hi/lo) ----
    unsigned pah[4][4], pal[4][4];
    #pragma unroll
    for (int kk = 0; kk < 4; kk++) {
        int t0 = 2 * kk, t1 = 2 * kk + 1;
        __half2 hh; float2 bk;
        hh = __floats2half2_rn(C[t0][0], C[t0][1]); pah[kk][0] = h2u(hh); bk = __half22float2(hh);
        pal[kk][0] = h2u(__floats2half2_rn(C[t0][0] - bk.x, C[t0][1] - bk.y));
        hh = __floats2half2_rn(C[t0][2], C[t0][3]); pah[kk][1] = h2u(hh); bk = __half22float2(hh);
        pal[kk][1] = h2u(__floats2half2_rn(C[t0][2] - bk.x, C[t0][3] - bk.y));
        hh = __floats2half2_rn(C[t1][0], C[t1][1]); pah[kk][2] = h2u(hh); bk = __half22float2(hh);
        pal[kk][2] = h2u(__floats2half2_rn(C[t1][0] - bk.x, C[t1][1] - bk.y));
        hh = __floats2half2_rn(C[t1][2], C[t1][3]); pah[kk][3] = h2u(hh); bk = __half22float2(hh);
        pal[kk][3] = h2u(__floats2half2_rn(C[t1][2] - bk.x, C[t1][3] - bk.y));
    }

    // ================= P@V (2-pass: P hi/lo x V hi) =================
    float O[8][4];
    #pragma unroll
    for (int nt = 0; nt < 8; nt++)
        #pragma unroll
        for (int e = 0; e < 4; e++) O[nt][e] = 0.f;

    #pragma unroll
    for (int kk = 0; kk < 4; kk++) {
        unsigned vRow = (unsigned)((jh * 64 + kk * 16 + qk8 + lr) * 144 + qf16);
        #pragma unroll
        for (int dp = 0; dp < 4; dp++) {
            unsigned vh0, vh1, vh2, vh3;
            ldsm_x4t(vh0, vh1, vh2, vh3, VhiB + vRow + dp * 32);
            mma16816(O[2*dp],   pah[kk][0], pah[kk][1], pah[kk][2], pah[kk][3], vh0, vh1);
            mma16816(O[2*dp],   pal[kk][0], pal[kk][1], pal[kk][2], pal[kk][3], vh0, vh1);
            mma16816(O[2*dp+1], pah[kk][0], pah[kk][1], pah[kk][2], pah[kk][3], vh2, vh3);
            mma16816(O[2*dp+1], pal[kk][0], pal[kk][1], pal[kk][2], pal[kk][3], vh2, vh3);
        }
    }

    // ---- combine j-halves via pbuf (overlay on Khi), write g_o ----
    __syncthreads();
    if (jh == 1) {
        #pragma unroll
        for (int nt = 0; nt < 8; nt++) {
            unsigned o0 = PbB + ((unsigned)(r0 * 66 + nt * 8 + 2 * tig) << 2);
            unsigned o1 = PbB + ((unsigned)(r1 * 66 + nt * 8 + 2 * tig) << 2);
            sts64f(o0, O[nt][0], O[nt][1]);
            sts64f(o1, O[nt][2], O[nt][3]);
        }
    }
    __syncthreads();
    if (jh == 0) {
        size_t ob0 = ((size_t)(b * NH + h) * SS + idi0) * DD;
        size_t ob1 = ((size_t)(b * NH + h) * SS + idi1) * DD;
        #pragma unroll
        for (int nt = 0; nt < 8; nt++) {
            int d = nt * 8 + 2 * tig;
            float2 u0 = lds64f(PbB + ((unsigned)(r0 * 66 + d) << 2));
            float2 u1 = lds64f(PbB + ((unsigned)(r1 * 66 + d) << 2));
            float2 w0 = make_float2((O[nt][0] + u0.x) * rinv0, (O[nt][1] + u0.y) * rinv0);
            float2 w1 = make_float2((O[nt][2] + u1.x) * rinv1, (O[nt][3] + u1.y) * rinv1);
            *(float2*)(g_o + ob0 + d) = w0;
            *(float2*)(g_o + ob1 + d) = w1;
        }
    }
}

// =============================================================================
// K4: combine hash rounds (DRAM-bound, unchanged)
// =============================================================================
__global__ __launch_bounds__(256) void combine_kernel(float* __restrict__ out)
{
    int gid = blockIdx.x * 256 + threadIdx.x;
    int d4  = gid & 15;
    int bt  = gid >> 4;
    int b   = bt >> 12;
    int t   = bt & 4095;

    float l[8]; float m = -3.4e38f;
    #pragma unroll
    for (int h = 0; h < 8; h++) { l[h] = g_lse[(b * NH + h) * SS + t]; m = fmaxf(m, l[h]); }
    float w[8]; float Z = 0.f;
    #pragma unroll
    for (int h = 0; h < 8; h++) { w[h] = __expf(l[h] - m); Z += w[h]; }
    float invZ = 1.0f / Z;

    float4 a = {0,0,0,0};
    #pragma unroll
    for (int h = 0; h < 8; h++) {
        float4 ov = *((const float4*)(g_o + ((size_t)(b * NH + h) * SS + t) * DD) + d4);
        a.x = fmaf(w[h], ov.x, a.x);
        a.y = fmaf(w[h], ov.y, a.y);
        a.z = fmaf(w[h], ov.z, a.z);
        a.w = fmaf(w[h], ov.w, a.w);
    }
    a.x *= invZ; a.y *= invZ; a.z *= invZ; a.w *= invZ;
    ((float4*)out)[(size_t)bt * 16 + d4] = a;
}

// =============================================================================
extern "C" void kernel_launch(void* const* d_in, const int* in_sizes, int n_in,
                              void* d_out, int out_size)
{
    const float* qk  = (const float*)d_in[0];
    const float* v   = (const float*)d_in[1];
    const float* rot = (const float*)d_in[2];
    float* out = (float*)d_out;

    cudaFuncSetAttribute(hash_kernel, cudaFuncAttributeMaxDynamicSharedMemorySize, 65536);
    cudaFuncSetAttribute(attn_kernel, cudaFuncAttributeMaxDynamicSharedMemorySize, ATT_SMEM_BYTES);

    hash_kernel<<<dim3(SS / 256, BB), 256, 65536>>>(qk, rot);
    sort_kernel<<<BB * NH, 128>>>();
    attn_kernel<<<dim3(512, BB), 256, ATT_SMEM_BYTES>>>(qk, v);
    combine_kernel<<<(BB * SS * 16) / 256, 256>>>(out);
}

// round 17
// speedup vs baseline: 1.4404x; 1.0562x over previous
#include <cuda_runtime.h>
#include <cuda_fp16.h>

#define BB 16
#define SS 4096
#define DD 64
#define NH 8
#define NB 64

typedef unsigned long long ull;

// ---- packed f32x2 helpers (hash kernel) ----
#define LDSV2(a,b,addr) asm volatile("ld.shared.v2.u64 {%0,%1},[%2];" : "=l"(a),"=l"(b) : "r"(addr))
#define FMA2(d,a,b,c)   asm("fma.rn.f32x2 %0,%1,%2,%3;" : "=l"(d) : "l"(a),"l"(b),"l"(c))
#define PK2(d,lo,hi)    asm("mov.b64 %0,{%1,%2};" : "=l"(d) : "f"(lo),"f"(hi))
#define UPK2(lo,hi,d)   asm("mov.b64 {%0,%1},%2;" : "=f"(lo),"=f"(hi) : "l"(d))

__device__ __forceinline__ unsigned smaddr(const void* p) {
    unsigned a;
    asm("{ .reg .u64 t; cvta.to.shared.u64 t, %1; cvt.u32.u64 %0, t; }" : "=r"(a) : "l"(p));
    return a;
}
__device__ __forceinline__ void sts64u(unsigned a, unsigned v0, unsigned v1) {
    asm volatile("st.shared.v2.b32 [%0],{%1,%2};" :: "r"(a), "r"(v0), "r"(v1));
}
__device__ __forceinline__ void sts64f(unsigned a, float x, float y) {
    asm volatile("st.shared.v2.f32 [%0],{%1,%2};" :: "r"(a), "f"(x), "f"(y));
}
__device__ __forceinline__ float2 lds64f(unsigned a) {
    float2 r; asm volatile("ld.shared.v2.f32 {%0,%1},[%2];" : "=f"(r.x), "=f"(r.y) : "r"(a)); return r;
}
__device__ __forceinline__ void ldsm_x4(unsigned& d0, unsigned& d1, unsigned& d2, unsigned& d3, unsigned a) {
    asm volatile("ldmatrix.sync.aligned.m8n8.x4.shared.b16 {%0,%1,%2,%3}, [%4];"
                 : "=r"(d0), "=r"(d1), "=r"(d2), "=r"(d3) : "r"(a));
}
__device__ __forceinline__ void ldsm_x4t(unsigned& d0, unsigned& d1, unsigned& d2, unsigned& d3, unsigned a) {
    asm volatile("ldmatrix.sync.aligned.m8n8.x4.trans.shared.b16 {%0,%1,%2,%3}, [%4];"
                 : "=r"(d0), "=r"(d1), "=r"(d2), "=r"(d3) : "r"(a));
}
__device__ __forceinline__ void mma16816(float* c, unsigned a0, unsigned a1, unsigned a2, unsigned a3,
                                         unsigned b0, unsigned b1) {
    asm volatile("mma.sync.aligned.m16n8k16.row.col.f32.f16.f16.f32 "
                 "{%0,%1,%2,%3}, {%4,%5,%6,%7}, {%8,%9}, {%0,%1,%2,%3};"
                 : "+f"(c[0]), "+f"(c[1]), "+f"(c[2]), "+f"(c[3])
                 : "r"(a0), "r"(a1), "r"(a2), "r"(a3), "r"(b0), "r"(b1));
}
__device__ __forceinline__ unsigned h2u(__half2 h) { return *reinterpret_cast<unsigned*>(&h); }

// ---------------- scratch ----------------
__device__ int    g_buckets[BB * NH * SS];
__device__ int    g_st[BB * NH * SS];
__device__ float  g_lse[BB * NH * SS];
__device__ __half g_o[(size_t)BB * NH * SS * DD];   // per-round outputs, fp16

// =============================================================================
// K1: LSH hashing (fp32 — bucket argmax must track reference)
// =============================================================================
__global__ __launch_bounds__(256) void hash_kernel(const float* __restrict__ qk,
                                                   const float* __restrict__ rot)
{
    extern __shared__ float rs[];
    int b   = blockIdx.y;
    int tid = threadIdx.x;
    const float* rg = rot + (size_t)b * DD * NH * 32;
    #pragma unroll
    for (int k = 0; k < 64; k++) rs[tid + k * 256] = rg[tid + k * 256];
    __syncthreads();

    int t = blockIdx.x * 256 + tid;
    float q[64];
    const float4* qg = (const float4*)(qk + ((size_t)b * SS + t) * DD);
    #pragma unroll
    for (int c = 0; c < 16; c++) {
        float4 u = qg[c];
        q[4*c] = u.x; q[4*c+1] = u.y; q[4*c+2] = u.z; q[4*c+3] = u.w;
    }

    unsigned rsb = smaddr(rs);

    #pragma unroll 1
    for (int h = 0; h < NH; h++) {
        ull va[16];
        #pragma unroll
        for (int k = 0; k < 16; k++) va[k] = 0ull;
        unsigned hb = rsb + h * 128;
        #pragma unroll 4
        for (int f = 0; f < 64; f++) {
            ull q2; PK2(q2, q[f], q[f]);
            unsigned rb = hb + f * 1024;
            #pragma unroll
            for (int c = 0; c < 8; c++) {
                ull r0, r1; LDSV2(r0, r1, rb + c * 16);
                FMA2(va[2*c],   q2, r0, va[2*c]);
                FMA2(va[2*c+1], q2, r1, va[2*c+1]);
            }
        }
        float vals[32];
        #pragma unroll
        for (int k = 0; k < 16; k++) UPK2(vals[2*k], vals[2*k+1], va[k]);
        float best = vals[0]; int arg = 0;
        #pragma unroll
        for (int i = 1; i < 32; i++) if (vals[i] > best) { best = vals[i]; arg = i; }
        #pragma unroll
        for (int i = 0; i < 32; i++) { float vv = -vals[i]; if (vv > best) { best = vv; arg = 32 + i; } }
        g_buckets[(b * NH + h) * SS + t] = arg;
    }
}

// =============================================================================
// K2: stable counting sort per (b,h)
// =============================================================================
__global__ __launch_bounds__(128) void sort_kernel()
{
    __shared__ int hist[64 * 130];
    __shared__ int base[64];
    int bh  = blockIdx.x;
    int tid = threadIdx.x;

    for (int k = tid; k < 64 * 130; k += 128) hist[k] = 0;
    __syncthreads();

    const int* bks = g_buckets + bh * SS;
    int myb[32];
    #pragma unroll
    for (int k = 0; k < 32; k++) {
        int bb = bks[tid * 32 + k];
        myb[k] = bb;
        hist[bb * 130 + tid] += 1;
    }
    __syncthreads();

    if (tid < 64) {
        int run = 0;
        for (int j = 0; j < 128; j++) {
            int vv = hist[tid * 130 + j];
            hist[tid * 130 + j] = run;
            run += vv;
        }
        base[tid] = run;
    }
    __syncthreads();
    if (tid == 0) {
        int run = 0;
        for (int u = 0; u < 64; u++) { int vv = base[u]; base[u] = run; run += vv; }
    }
    __syncthreads();

    int* st = g_st + bh * SS;
    #pragma unroll
    for (int k = 0; k < 32; k++) {
        int bb  = myb[k];
        int off = hist[bb * 130 + tid];
        hist[bb * 130 + tid] = off + 1;
        st[base[bb] + off] = tid * 32 + k;
    }
}

// =============================================================================
// K3: HMMA attention. QK 3-pass fp16 split; PV 1-pass (P hi x V hi).
// smem bytes (row stride 72 halves = 144 B):
//   Khi [128][72]h @0      (18432)  <- pbuf[64][66]f overlay at epilogue
//   Klo [128][72]h @18432  (18432)
//   Vhi [128][72]h @36864  (18432)  (row-major [j][d])
//   qn f[64] @55296 | red f[128] @55552 | ids i[128] @56064
// total 56576 B -> 3 CTAs/SM.
// =============================================================================
#define SM_KLO_OFF 18432
#define SM_VHI_OFF 36864
#define SM_QN_OFF  55296
#define SM_RED_OFF 55552
#define SM_IDS_OFF 56064
#define ATT_SMEM_BYTES 56576

__global__ __launch_bounds__(256, 3) void attn_kernel(const float* __restrict__ qk,
                                                      const float* __restrict__ vin)
{
    extern __shared__ char smc[];
    float* qn  = (float*)(smc + SM_QN_OFF);
    float* red = (float*)(smc + SM_RED_OFF);
    int*   ids = (int*)(smc + SM_IDS_OFF);

    unsigned SB   = smaddr(smc);
    unsigned KhiB = SB;
    unsigned KloB = SB + SM_KLO_OFF;
    unsigned VhiB = SB + SM_VHI_OFF;
    unsigned PbB  = SB;

    int b   = blockIdx.y;
    int c   = blockIdx.x;
    int tid = threadIdx.x;
    int h   = c >> 6,  lc  = c & 63;
    int pcn = (c + 511) & 511;
    int ph  = pcn >> 6, plc = pcn & 63;

    if (tid < 128) {
        int rr = tid;
        ids[rr] = (rr < 64) ? g_st[(b * NH + h)  * SS + lc  * 64 + rr]
                            : g_st[(b * NH + ph) * SS + plc * 64 + (rr - 64)];
    }
    __syncthreads();

    // ---- gather: K-hat hi/lo + V hi (fp16), vectorized STS ----
    {
        int r = tid >> 1, part = tid & 1;
        int t = ids[r];
        int f0 = part * 32;
        const float4* srck = (const float4*)(qk  + ((size_t)b * SS + t) * DD) + part * 8;
        const float4* srcv = (const float4*)(vin + ((size_t)b * SS + t) * DD) + part * 8;
        float4 xr[8], vr[8];
        float  ssq = 0.f;
        #pragma unroll
        for (int c4 = 0; c4 < 8; c4++) {
            float4 x = srck[c4]; xr[c4] = x;
            ssq += x.x * x.x + x.y * x.y + x.z * x.z + x.w * x.w;
            vr[c4] = srcv[c4];
        }
        ssq += __shfl_xor_sync(0xffffffffu, ssq, 1);
        float norm = sqrtf(ssq);
        float inv  = 1.0f / fmaxf(norm, 1e-12f);
        #pragma unroll
        for (int c4 = 0; c4 < 8; c4++) {
            float k0 = xr[c4].x * inv, k1 = xr[c4].y * inv;
            float k2 = xr[c4].z * inv, k3 = xr[c4].w * inv;
            unsigned off = ((unsigned)(r * 72 + f0 + 4 * c4)) << 1;
            __half2 h01 = __floats2half2_rn(k0, k1);
            __half2 h23 = __floats2half2_rn(k2, k3);
            sts64u(KhiB + off, h2u(h01), h2u(h23));
            float2 b01 = __half22float2(h01);
            float2 b23 = __half22float2(h23);
            sts64u(KloB + off,
                   h2u(__floats2half2_rn(k0 - b01.x, k1 - b01.y)),
                   h2u(__floats2half2_rn(k2 - b23.x, k3 - b23.y)));
            sts64u(VhiB + off,
                   h2u(__floats2half2_rn(vr[c4].x, vr[c4].y)),
                   h2u(__floats2half2_rn(vr[c4].z, vr[c4].w)));
        }
        if (part == 0 && r < 64) qn[r] = norm * 0.125f;
    }
    __syncthreads();

    int warp = tid >> 5, lane = tid & 31;
    int g = lane >> 2, tig = lane & 3;
    int mt = warp & 3, jh = warp >> 2;
    int r0 = mt * 16 + g, r1 = r0 + 8;

    int lq  = lane >> 3;
    int lr  = lane & 7;
    int qk8 = (lq & 1) * 8;
    int qf16 = (lq >> 1) * 16;

    unsigned aAdr = (unsigned)((mt * 16 + qk8 + lr) * 144 + qf16);
    unsigned bAdr[4];
    #pragma unroll
    for (int np = 0; np < 4; np++)
        bAdr[np] = (unsigned)((jh * 64 + np * 16 + qk8 + lr) * 144 + qf16);

    // ================= QK^T (3-pass split HMMA) =================
    float C[8][4];
    #pragma unroll
    for (int nt = 0; nt < 8; nt++)
        #pragma unroll
        for (int e = 0; e < 4; e++) C[nt][e] = 0.f;

    #pragma unroll
    for (int kk = 0; kk < 4; kk++) {
        unsigned ah0, ah1, ah2, ah3, al0, al1, al2, al3;
        ldsm_x4(ah0, ah1, ah2, ah3, KhiB + aAdr + kk * 32);
        ldsm_x4(al0, al1, al2, al3, KloB + aAdr + kk * 32);
        #pragma unroll
        for (int np = 0; np < 4; np++) {
            unsigned bh0, bh1, bh2, bh3, bl0, bl1, bl2, bl3;
            ldsm_x4(bh0, bh1, bh2, bh3, KhiB + bAdr[np] + kk * 32);
            ldsm_x4(bl0, bl1, bl2, bl3, KloB + bAdr[np] + kk * 32);
            mma16816(C[2*np],   ah0, ah1, ah2, ah3, bh0, bh2);
            mma16816(C[2*np],   al0, al1, al2, al3, bh0, bh2);
            mma16816(C[2*np],   ah0, ah1, ah2, ah3, bl0, bl2);
            mma16816(C[2*np+1], ah0, ah1, ah2, ah3, bh1, bh3);
            mma16816(C[2*np+1], al0, al1, al2, al3, bh1, bh3);
            mma16816(C[2*np+1], ah0, ah1, ah2, ah3, bl1, bl3);
        }
    }

    // ---- scale + self-mask ----
    float q0 = qn[r0], q1 = qn[r1];
    int idi0 = ids[r0], idi1 = ids[r1];
    #pragma unroll
    for (int nt = 0; nt < 8; nt++) {
        int jj = jh * 64 + nt * 8 + 2 * tig;
        int e0 = ids[jj], e1 = ids[jj + 1];
        C[nt][0] *= q0; C[nt][1] *= q0;
        C[nt][2] *= q1; C[nt][3] *= q1;
        if (idi0 == e0) C[nt][0] = -50000.0f;
        if (idi0 == e1) C[nt][1] = -50000.0f;
        if (idi1 == e0) C[nt][2] = -50000.0f;
        if (idi1 == e1) C[nt][3] = -50000.0f;
    }

    // ---- softmax (regs + shfl + cross-warp red) ----
    float m0 = -3.4e38f, m1 = -3.4e38f;
    #pragma unroll
    for (int nt = 0; nt < 8; nt++) {
        m0 = fmaxf(m0, fmaxf(C[nt][0], C[nt][1]));
        m1 = fmaxf(m1, fmaxf(C[nt][2], C[nt][3]));
    }
    m0 = fmaxf(m0, __shfl_xor_sync(0xffffffffu, m0, 1));
    m0 = fmaxf(m0, __shfl_xor_sync(0xffffffffu, m0, 2));
    m1 = fmaxf(m1, __shfl_xor_sync(0xffffffffu, m1, 1));
    m1 = fmaxf(m1, __shfl_xor_sync(0xffffffffu, m1, 2));
    if (tig == 0) { red[r0 * 2 + jh] = m0; red[r1 * 2 + jh] = m1; }
    __syncthreads();
    float rm0 = fmaxf(red[r0 * 2], red[r0 * 2 + 1]);
    float rm1 = fmaxf(red[r1 * 2], red[r1 * 2 + 1]);
    __syncthreads();

    float s0 = 0.f, s1 = 0.f;
    #pragma unroll
    for (int nt = 0; nt < 8; nt++) {
        C[nt][0] = __expf(C[nt][0] - rm0);
        C[nt][1] = __expf(C[nt][1] - rm0);
        C[nt][2] = __expf(C[nt][2] - rm1);
        C[nt][3] = __expf(C[nt][3] - rm1);
        s0 += C[nt][0] + C[nt][1];
        s1 += C[nt][2] + C[nt][3];
    }
    s0 += __shfl_xor_sync(0xffffffffu, s0, 1);
    s0 += __shfl_xor_sync(0xffffffffu, s0, 2);
    s1 += __shfl_xor_sync(0xffffffffu, s1, 1);
    s1 += __shfl_xor_sync(0xffffffffu, s1, 2);
    if (tig == 0) { red[r0 * 2 + jh] = s0; red[r1 * 2 + jh] = s1; }
    __syncthreads();
    float rs0 = red[r0 * 2] + red[r0 * 2 + 1];
    float rs1 = red[r1 * 2] + red[r1 * 2 + 1];
    if (jh == 0 && tig == 0) {
        g_lse[(b * NH + h) * SS + idi0] = rm0 + __logf(rs0);
        g_lse[(b * NH + h) * SS + idi1] = rm1 + __logf(rs1);
    }
    float rinv0 = 1.0f / rs0, rinv1 = 1.0f / rs1;

    // ---- P: C fragments -> A fragments (fp16 hi only) ----
    unsigned pah[4][4];
    #pragma unroll
    for (int kk = 0; kk < 4; kk++) {
        int t0 = 2 * kk, t1 = 2 * kk + 1;
        pah[kk][0] = h2u(__floats2half2_rn(C[t0][0], C[t0][1]));
        pah[kk][1] = h2u(__floats2half2_rn(C[t0][2], C[t0][3]));
        pah[kk][2] = h2u(__floats2half2_rn(C[t1][0], C[t1][1]));
        pah[kk][3] = h2u(__floats2half2_rn(C[t1][2], C[t1][3]));
    }

    // ================= P@V (1-pass: P hi x V hi) =================
    float O[8][4];
    #pragma unroll
    for (int nt = 0; nt < 8; nt++)
        #pragma unroll
        for (int e = 0; e < 4; e++) O[nt][e] = 0.f;

    #pragma unroll
    for (int kk = 0; kk < 4; kk++) {
        unsigned vRow = (unsigned)((jh * 64 + kk * 16 + qk8 + lr) * 144 + qf16);
        #pragma unroll
        for (int dp = 0; dp < 4; dp++) {
            unsigned vh0, vh1, vh2, vh3;
            ldsm_x4t(vh0, vh1, vh2, vh3, VhiB + vRow + dp * 32);
            mma16816(O[2*dp],   pah[kk][0], pah[kk][1], pah[kk][2], pah[kk][3], vh0, vh1);
            mma16816(O[2*dp+1], pah[kk][0], pah[kk][1], pah[kk][2], pah[kk][3], vh2, vh3);
        }
    }

    // ---- combine j-halves via pbuf (overlay on Khi), write g_o fp16 ----
    __syncthreads();
    if (jh == 1) {
        #pragma unroll
        for (int nt = 0; nt < 8; nt++) {
            unsigned o0 = PbB + ((unsigned)(r0 * 66 + nt * 8 + 2 * tig) << 2);
            unsigned o1 = PbB + ((unsigned)(r1 * 66 + nt * 8 + 2 * tig) << 2);
            sts64f(o0, O[nt][0], O[nt][1]);
            sts64f(o1, O[nt][2], O[nt][3]);
        }
    }
    __syncthreads();
    if (jh == 0) {
        size_t ob0 = ((size_t)(b * NH + h) * SS + idi0) * DD;
        size_t ob1 = ((size_t)(b * NH + h) * SS + idi1) * DD;
        #pragma unroll
        for (int nt = 0; nt < 8; nt++) {
            int d = nt * 8 + 2 * tig;
            float2 u0 = lds64f(PbB + ((unsigned)(r0 * 66 + d) << 2));
            float2 u1 = lds64f(PbB + ((unsigned)(r1 * 66 + d) << 2));
            __half2 w0 = __floats2half2_rn((O[nt][0] + u0.x) * rinv0, (O[nt][1] + u0.y) * rinv0);
            __half2 w1 = __floats2half2_rn((O[nt][2] + u1.x) * rinv1, (O[nt][3] + u1.y) * rinv1);
            *(unsigned*)(g_o + ob0 + d) = h2u(w0);
            *(unsigned*)(g_o + ob1 + d) = h2u(w1);
        }
    }
}

// =============================================================================
// K4: combine hash rounds (fp16 g_o reads; 8 threads/token, 16B loads)
// =============================================================================
__global__ __launch_bounds__(256) void combine_kernel(float* __restrict__ out)
{
    int gid = blockIdx.x * 256 + threadIdx.x;    // B*S*8 threads
    int d8  = (gid & 7) * 8;
    int bt  = gid >> 3;
    int b   = bt >> 12;
    int t   = bt & 4095;

    float l[8]; float m = -3.4e38f;
    #pragma unroll
    for (int h = 0; h < 8; h++) { l[h] = g_lse[(b * NH + h) * SS + t]; m = fmaxf(m, l[h]); }
    float w[8]; float Z = 0.f;
    #pragma unroll
    for (int h = 0; h < 8; h++) { w[h] = __expf(l[h] - m); Z += w[h]; }
    float invZ = 1.0f / Z;

    float a[8];
    #pragma unroll
    for (int e = 0; e < 8; e++) a[e] = 0.f;
    #pragma unroll
    for (int h = 0; h < 8; h++) {
        uint4 pv = *(const uint4*)(g_o + ((size_t)(b * NH + h) * SS + t) * DD + d8);
        float2 f0 = __half22float2(*reinterpret_cast<__half2*>(&pv.x));
        float2 f1 = __half22float2(*reinterpret_cast<__half2*>(&pv.y));
        float2 f2 = __half22float2(*reinterpret_cast<__half2*>(&pv.z));
        float2 f3 = __half22float2(*reinterpret_cast<__half2*>(&pv.w));
        a[0] = fmaf(w[h], f0.x, a[0]); a[1] = fmaf(w[h], f0.y, a[1]);
        a[2] = fmaf(w[h], f1.x, a[2]); a[3] = fmaf(w[h], f1.y, a[3]);
        a[4] = fmaf(w[h], f2.x, a[4]); a[5] = fmaf(w[h], f2.y, a[5]);
        a[6] = fmaf(w[h], f3.x, a[6]); a[7] = fmaf(w[h], f3.y, a[7]);
    }
    float4* dst = (float4*)(out + (size_t)bt * DD + d8);
    dst[0] = make_float4(a[0] * invZ, a[1] * invZ, a[2] * invZ, a[3] * invZ);
    dst[1] = make_float4(a[4] * invZ, a[5] * invZ, a[6] * invZ, a[7] * invZ);
}

// =============================================================================
extern "C" void kernel_launch(void* const* d_in, const int* in_sizes, int n_in,
                              void* d_out, int out_size)
{
    const float* qk  = (const float*)d_in[0];
    const float* v   = (const float*)d_in[1];
    const float* rot = (const float*)d_in[2];
    float* out = (float*)d_out;

    cudaFuncSetAttribute(hash_kernel, cudaFuncAttributeMaxDynamicSharedMemorySize, 65536);
    cudaFuncSetAttribute(attn_kernel, cudaFuncAttributeMaxDynamicSharedMemorySize, ATT_SMEM_BYTES);

    hash_kernel<<<dim3(SS / 256, BB), 256, 65536>>>(qk, rot);
    sort_kernel<<<BB * NH, 128>>>();
    attn_kernel<<<dim3(512, BB), 256, ATT_SMEM_BYTES>>>(qk, v);
    combine_kernel<<<(BB * SS * 8) / 256, 256>>>(out);
}